// round 16
// baseline (speedup 1.0000x reference)
#include <cuda_runtime.h>

// ---------------------------------------------------------------------------
// SpatialFrequencyLoss: sum_i w_i * mean( (LoG_i * (input - target))^2 )
// LoG kernel is rank-3 separable:  a = f (x) u  +  u (x) f  -  c * ones
// sigma0-2 (K=5,11,21): ONE fused kernel per 64x64 tile — stage the sigma2
//   halo (84x84) once; per sigma, row+col in two 32-column halves.
// sigma3-5 (K=39,77,155): quarter-res cascade, one merged kernel per tile.
// No final kernel: a device completion counter makes the LAST block write
//   the weighted loss and reset the accumulators (clean state per replay).
// fused_all launches immediately (no dependency on down4); down4+fusedq on a
//   side stream overlap it completely.
// ---------------------------------------------------------------------------

namespace {
constexpr int Hh = 512, Ww = 512, NCc = 4 * 3;
constexpr int NPIX = NCc * Hh * Ww;      // 3,145,728
constexpr int W4 = 128, GPAD4 = 20;
constexpr int DP4 = W4 + 2 * GPAD4;      // 168 padded dim for D4
constexpr int NT = 256;                  // threads per fused block
constexpr int PST = 10;                  // full-res staging halo (sigma2)
constexpr int IWST = 64 + 2 * PST;       // 84
constexpr int PQ  = 20;                  // quarter staging halo (sigma5 PL)
constexpr int IWQ = 64 + 2 * PQ - 1;     // 103 (= 63 + K4max)
constexpr unsigned TOTAL_BLOCKS = 768u + 48u;   // fused_all + fusedq_all
}

__device__ float  g_Dq[NCc * DP4 * DP4]; // padded quarter-res diff plane
__device__ double g_acc[6];              // zero-initialized; reset by last block
__device__ unsigned g_done = 0;          // completion counter

// ---------------- f32x2 packed helpers --------------------------------------

__device__ __forceinline__ unsigned long long pk2(float lo, float hi) {
    unsigned long long r;
    asm("mov.b64 %0, {%1, %2};" : "=l"(r) : "f"(lo), "f"(hi));
    return r;
}
__device__ __forceinline__ unsigned long long ffma2(unsigned long long a,
                                                    unsigned long long b,
                                                    unsigned long long c) {
    unsigned long long d;
    asm("fma.rn.f32x2 %0, %1, %2, %3;" : "=l"(d) : "l"(a), "l"(b), "l"(c));
    return d;
}
__device__ __forceinline__ float2 upk(unsigned long long a) {
    float2 v;
    asm("mov.b64 {%0, %1}, %2;" : "=f"(v.x), "=f"(v.y) : "l"(a));
    return v;
}

// ---------------- compile-time taps ----------------------------------------

__host__ __device__ constexpr double cexp(double x) {
    double r = x; int n = 0;
    while (r < -0.5) { r += 1.0; ++n; }
    double term = 1.0, sum = 1.0;
    for (int i = 1; i < 30; ++i) { term *= r / (double)i; sum += term; }
    for (int i = 0; i < n; ++i) sum /= 2.71828182845904523536028747135266;
    return sum;
}
__host__ __device__ constexpr double u_at(int x, int P, double ss) {
    if (x < -P || x > P) return 0.0;
    return cexp(-((double)x * x) / (2.0 * ss));
}
__host__ __device__ constexpr double f_at(int x, int P, double ss, double norm) {
    if (x < -P || x > P) return 0.0;
    return ((double)x * x - ss) * cexp(-((double)x * x) / (2.0 * ss)) * norm;
}

template<int K> struct TapsT { float f[K]; float h[K]; float c; };

template<int K>
__host__ __device__ constexpr TapsT<K> make_taps(double sigma) {
    TapsT<K> T{};
    const double ss = sigma * sigma;
    const double norm = 1.0 / (2.0 * 3.14159265358979323846 * ss * ss);
    const int P = K / 2;
    double Sf = 0.0, Sh = 0.0;
    for (int i = 0; i < K; ++i) {
        const double fv = f_at(i - P, P, ss, norm);
        const double uv = u_at(i - P, P, ss);
        T.f[i] = (float)fv;
        T.h[i] = (float)uv;
        Sf += fv; Sh += uv;
    }
    T.c = (float)(2.0 * Sf * Sh / ((double)K * (double)K));
    return T;
}

template<int KS> struct TapsQ { float F[KS]; float U[KS]; float c; };

template<int KS>
__host__ __device__ constexpr TapsQ<KS> make_tapsQ(double sigma, int K, int PL) {
    TapsQ<KS> T{};
    const double ss = sigma * sigma;
    const double norm = 1.0 / (2.0 * 3.14159265358979323846 * ss * ss);
    const int P = K / 2;
    for (int t = 0; t < KS; ++t) {
        const int v = t - PL;
        double Fv = 0.0, Uv = 0.0;
        for (int j = 0; j < 4; ++j) {
            Fv += f_at(4 * v + j, P, ss, norm);
            Uv += u_at(4 * v + j, P, ss);
        }
        T.F[t] = (float)Fv;
        T.U[t] = (float)Uv;
    }
    double Sf = 0.0, Sh = 0.0;
    for (int x = -P; x <= P; ++x) { Sf += f_at(x, P, ss, norm); Sh += u_at(x, P, ss); }
    T.c = (float)(32.0 * Sf * Sh / ((double)K * (double)K));
    return T;
}

template<int SI> struct Cfg;
template<> struct Cfg<0> { static constexpr int K = 5;  static constexpr double S = 0.6; };
template<> struct Cfg<1> { static constexpr int K = 11; static constexpr double S = 1.2; };
template<> struct Cfg<2> { static constexpr int K = 21; static constexpr double S = 2.4; };

template<int SI> struct CQ;
template<> struct CQ<3> { static constexpr int K = 39;  static constexpr double S = 4.8;  static constexpr int K4 = 10; static constexpr int PL = 5;  };
template<> struct CQ<4> { static constexpr int K = 77;  static constexpr double S = 9.6;  static constexpr int K4 = 20; static constexpr int PL = 10; };
template<> struct CQ<5> { static constexpr int K = 155; static constexpr double S = 19.2; static constexpr int K4 = 40; static constexpr int PL = 20; };

// merged full-res SMEM layout (half-width col buffers)
struct MSz {
    static constexpr int IWp    = IWST;                        // 84 (mult of 4)
    static constexpr int OFF_FH = (IWST * IWp * 4 + 15) & ~15;
    static constexpr int OFF_A1 = OFF_FH + IWST * 32 * 8;
    static constexpr int BYTES  = OFF_A1 + IWST * 32 * 4;      // ~60.5 KB
};
// merged quarter-res SMEM layout (full-width col buffers, sized for sigma5)
struct QM {
    static constexpr int IWp    = (IWQ + 3) & ~3;              // 104
    static constexpr int OFF_FH = (IWQ * IWp * 4 + 15) & ~15;
    static constexpr int OFF_A1 = OFF_FH + IWQ * 64 * 8;
    static constexpr int BYTES  = OFF_A1 + IWQ * 64 * 4;       // ~122 KB
};

__device__ __forceinline__ int refl(int i, int n) {
    if (i < 0) i = -i;
    if (i >= n) i = 2 * n - 2 - i;
    return i;
}

// ---------------- completion: last block writes the result -------------------

__device__ __forceinline__ void finish_block(float* __restrict__ out, int tid) {
    if (tid != 0) return;
    __threadfence();                       // make this block's atomics visible
    const unsigned old = atomicAdd(&g_done, 1u);
    if (old == TOTAL_BLOCKS - 1u) {
        const double w[6] = {600.0, 500.0, 400.0, 20.0, 10.0, 10.0};
        double l = 0.0;
        for (int i = 0; i < 3; ++i) l += w[i] * g_acc[i];
        for (int i = 3; i < 6; ++i) l += w[i] * 16.0 * g_acc[i];
        out[0] = (float)(l / (double)NPIX);
        for (int i = 0; i < 6; ++i) g_acc[i] = 0.0;   // clean for next replay
        g_done = 0u;
        __threadfence();
    }
}

// ---------------- quarter downsample (padded) --------------------------------

__global__ void down4_k(const float* __restrict__ a, const float* __restrict__ b) {
    const int img = blockIdx.y;
    const int uy  = blockIdx.x;
    const int wy  = uy - GPAD4;
    const float* __restrict__ A = a + img * (Hh * Ww);
    const float* __restrict__ B = b + img * (Hh * Ww);
    float* __restrict__ dst = g_Dq + (img * DP4 + uy) * DP4;
    const bool yin = (wy >= 0) && (wy < W4);

    for (int ux = threadIdx.x; ux < DP4; ux += blockDim.x) {
        const int wx = ux - GPAD4;
        float s = 0.f;
        if (yin && wx >= 0 && wx < W4) {
            const int base = (4 * wy) * Ww + 4 * wx;
#pragma unroll
            for (int r = 0; r < 4; ++r) {
                const float4 va = *reinterpret_cast<const float4*>(A + base + r * Ww);
                const float4 vb = *reinterpret_cast<const float4*>(B + base + r * Ww);
                s += (va.x - vb.x) + (va.y - vb.y) + (va.z - vb.z) + (va.w - vb.w);
            }
        } else {
#pragma unroll
            for (int r = 0; r < 4; ++r) {
                const int ry = refl(4 * wy + r, Hh);
#pragma unroll
                for (int cc = 0; cc < 4; ++cc) {
                    const int cx = refl(4 * wx + cc, Ww);
                    s += A[ry * Ww + cx] - B[ry * Ww + cx];
                }
            }
        }
        dst[ux] = 0.0625f * s;
    }
}

// ---------------- shared fused tile machinery --------------------------------

template<int KT, bool AL4, int IWp, int TPR>
__device__ __forceinline__ void tile_row_phase(
    const float* __restrict__ INs,
    unsigned long long* __restrict__ FHs, float* __restrict__ A1s,
    const float* __restrict__ tf, const float* __restrict__ th,
    int nrows, int tid)
{
    constexpr int OUTW = TPR * 8;
    const int x0   = (tid & (TPR - 1)) * 8;
    const int rgrp = tid / TPR;
    constexpr int RSTR = NT / TPR;
    for (int r = rgrp; r < nrows; r += RSTR) {
        const float* __restrict__ sr = INs + r * IWp + x0;

        float w[12];
        if (AL4) {
#pragma unroll
            for (int i = 0; i < 8; i += 4) {
                const float4 v = *reinterpret_cast<const float4*>(sr + i);
                w[i] = v.x; w[i + 1] = v.y; w[i + 2] = v.z; w[i + 3] = v.w;
            }
        } else {
#pragma unroll
            for (int i = 0; i < 8; ++i) w[i] = sr[i];
        }
        unsigned long long aFH[8];
#pragma unroll
        for (int o = 0; o < 8; ++o) aFH[o] = 0ull;
        float S = 0.f;

        constexpr int G = KT / 4, REM = KT % 4;
#pragma unroll
        for (int tg = 0; tg < G; ++tg) {
            if (AL4) {
                const float4 v = *reinterpret_cast<const float4*>(sr + 8 + 4 * tg);
                w[8] = v.x; w[9] = v.y; w[10] = v.z; w[11] = v.w;
            } else {
#pragma unroll
                for (int i = 0; i < 4; ++i) w[8 + i] = sr[8 + 4 * tg + i];
            }
#pragma unroll
            for (int j = 0; j < 4; ++j) {
                const int t = 4 * tg + j;
                const unsigned long long tp = pk2(tf[t], th[t]);
                S += w[j];
#pragma unroll
                for (int o = 0; o < 8; ++o) {
                    const unsigned long long dd = pk2(w[j + o], w[j + o]);
                    aFH[o] = ffma2(tp, dd, aFH[o]);
                }
            }
#pragma unroll
            for (int i = 0; i < 8; ++i) w[i] = w[i + 4];
        }
        if (REM >= 2) w[8] = sr[4 * G + 8];
        if (REM == 3) w[9] = sr[4 * G + 9];
#pragma unroll
        for (int j = 0; j < REM; ++j) {
            const int t = 4 * G + j;
            const unsigned long long tp = pk2(tf[t], th[t]);
            S += w[j];
#pragma unroll
            for (int o = 0; o < 8; ++o) {
                const unsigned long long dd = pk2(w[j + o], w[j + o]);
                aFH[o] = ffma2(tp, dd, aFH[o]);
            }
        }

        float box[8];
        box[0] = S;
#pragma unroll
        for (int o = 1; o < 8; ++o)
            box[o] = box[o - 1] - sr[o - 1] + sr[o + KT - 1];

        unsigned long long* __restrict__ fh = FHs + r * OUTW + x0;
        float* __restrict__ a1 = A1s + r * OUTW + x0;
#pragma unroll
        for (int o = 0; o < 8; ++o) {
            const float2 p = upk(aFH[o]);     // x = aF, y = aH
            fh[o] = pk2(p.y, p.x);            // store (aH, aF)
            a1[o] = box[o];
        }
    }
}

template<int KT, int OUTW, int R>
__device__ __forceinline__ float tile_col_phase(
    const unsigned long long* __restrict__ FHs, const float* __restrict__ A1s,
    const float* __restrict__ tf, const float* __restrict__ th,
    float cc, int tid)
{
    const int x  = tid & (OUTW - 1);
    const int y0 = (tid / OUTW) * R;
    const unsigned long long* __restrict__ fcol = FHs + x;
    const float* __restrict__ acol = A1s + x;

    unsigned long long ring[R], acc[R];
#pragma unroll
    for (int o = 0; o < R; ++o) acc[o] = 0ull;
#pragma unroll
    for (int j = 0; j < R - 1; ++j) ring[j] = fcol[(y0 + j) * OUTW];

#pragma unroll
    for (int t = 0; t < KT; ++t) {
        ring[(t + R - 1) & (R - 1)] = fcol[(y0 + t + R - 1) * OUTW];
        const unsigned long long tp = pk2(tf[t], th[t]);
#pragma unroll
        for (int o = 0; o < R; ++o)
            acc[o] = ffma2(tp, ring[(t + o) & (R - 1)], acc[o]);
    }

    float s0 = 0.f, s1 = 0.f, s2 = 0.f, s3 = 0.f;
    int j = 0;
#pragma unroll
    for (; j + 3 < KT; j += 4) {
        s0 += acol[(y0 + j) * OUTW];
        s1 += acol[(y0 + j + 1) * OUTW];
        s2 += acol[(y0 + j + 2) * OUTW];
        s3 += acol[(y0 + j + 3) * OUTW];
    }
#pragma unroll
    for (; j < KT; ++j) s0 += acol[(y0 + j) * OUTW];
    float box = (s0 + s1) + (s2 + s3), local = 0.f;

#pragma unroll
    for (int o = 0; o < R; ++o) {
        if (o) box += acol[(y0 + KT - 1 + o) * OUTW] - acol[(y0 + o - 1) * OUTW];
        const float2 p = upk(acc[o]);
        const float v = fmaf(-cc, box, p.x + p.y);
        local = fmaf(v, v, local);
    }
    return local;
}

__device__ __forceinline__ void tile_reduce(float local, int tid, int si) {
#pragma unroll
    for (int off = 16; off; off >>= 1)
        local += __shfl_xor_sync(0xffffffffu, local, off);
    __shared__ float ws[8];
    if ((tid & 31) == 0) ws[tid >> 5] = local;
    __syncthreads();
    if (tid == 0) {
        double tot = 0.0;
#pragma unroll
        for (int i = 0; i < 8; ++i) tot += (double)ws[i];
        atomicAdd(&g_acc[si], tot);
    }
}

// ---------------- merged full-res kernel (sigma0+1+2) ------------------------

template<int SI, bool AL4>
__device__ __forceinline__ void run_sigma_phases_fr(
    const float* __restrict__ IN, unsigned long long* __restrict__ FHs,
    float* __restrict__ A1s, int tid)
{
    constexpr int K = Cfg<SI>::K;
    constexpr TapsT<K> T = make_taps<K>(Cfg<SI>::S);
    constexpr int P  = K / 2;
    constexpr int dP = PST - P;
    constexpr int nrows = 64 + 2 * P;

    float local = 0.f;
#pragma unroll
    for (int h = 0; h < 2; ++h) {
        tile_row_phase<K, AL4, MSz::IWp, 4>(
            IN + dP * MSz::IWp + dP + 32 * h, FHs, A1s, T.f, T.h, nrows, tid);
        __syncthreads();
        local += tile_col_phase<K, 32, 8>(FHs, A1s, T.f, T.h, T.c, tid);
        __syncthreads();
    }
    tile_reduce(local, tid, SI);
}

__global__ void __launch_bounds__(NT) fused_all_k(const float* __restrict__ a,
                                                  const float* __restrict__ b,
                                                  float* __restrict__ out) {
    extern __shared__ char smem[];
    float* __restrict__ IN = reinterpret_cast<float*>(smem);
    unsigned long long* __restrict__ FHs =
        reinterpret_cast<unsigned long long*>(smem + MSz::OFF_FH);
    float* __restrict__ A1s = reinterpret_cast<float*>(smem + MSz::OFF_A1);

    const int tid = threadIdx.x;
    const int tx0 = blockIdx.x * 64, ty0 = blockIdx.y * 64;
    const int img = blockIdx.z;
    const float* __restrict__ A = a + img * (Hh * Ww);
    const float* __restrict__ B = b + img * (Hh * Ww);

    const bool interior = (tx0 >= PST) && (tx0 + 64 + PST <= Ww) &&
                          (ty0 >= PST) && (ty0 + 64 + PST <= Hh);
    if (interior) {
        const int base = (ty0 - PST) * Ww + (tx0 - PST);
        for (int idx = tid; idx < IWST * IWST; idx += NT) {
            const int r = idx / IWST, c = idx - r * IWST;
            const int gi = base + r * Ww + c;
            IN[r * MSz::IWp + c] = A[gi] - B[gi];
        }
    } else {
        for (int idx = tid; idx < IWST * IWST; idx += NT) {
            const int r = idx / IWST, c = idx - r * IWST;
            const int gi = refl(ty0 + r - PST, Hh) * Ww + refl(tx0 + c - PST, Ww);
            IN[r * MSz::IWp + c] = A[gi] - B[gi];
        }
    }
    __syncthreads();

    run_sigma_phases_fr<2, true >(IN, FHs, A1s, tid);   // dP = 0
    run_sigma_phases_fr<1, false>(IN, FHs, A1s, tid);   // dP = 5 (scalar)
    run_sigma_phases_fr<0, true >(IN, FHs, A1s, tid);   // dP = 8

    finish_block(out, tid);
}

// ---------------- merged quarter-res kernel (sigma3+4+5) ---------------------

template<int SI, bool AL4>
__device__ __forceinline__ void run_sigma_phases_q(
    const float* __restrict__ IN, unsigned long long* __restrict__ FHs,
    float* __restrict__ A1s, int tid)
{
    constexpr int K4 = CQ<SI>::K4;
    constexpr TapsQ<K4> T = make_tapsQ<K4>(CQ<SI>::S, CQ<SI>::K, CQ<SI>::PL);
    constexpr int dP = PQ - CQ<SI>::PL;
    constexpr int nrows = 63 + K4;

    tile_row_phase<K4, AL4, QM::IWp, 8>(
        IN + dP * QM::IWp + dP, FHs, A1s, T.F, T.U, nrows, tid);
    __syncthreads();
    const float local = tile_col_phase<K4, 64, 16>(FHs, A1s, T.F, T.U, T.c, tid);
    tile_reduce(local, tid, SI);
}

__global__ void __launch_bounds__(NT) fusedq_all_k(float* __restrict__ out) {
    extern __shared__ char smem[];
    float* __restrict__ IN = reinterpret_cast<float*>(smem);
    unsigned long long* __restrict__ FHs =
        reinterpret_cast<unsigned long long*>(smem + QM::OFF_FH);
    float* __restrict__ A1s = reinterpret_cast<float*>(smem + QM::OFF_A1);

    const int tid = threadIdx.x;
    const int tx0 = blockIdx.x * 64, ty0 = blockIdx.y * 64;
    const int img = blockIdx.z;
    const float* __restrict__ src =
        g_Dq + (img * DP4 + (ty0 - PQ + GPAD4)) * DP4 + (tx0 - PQ + GPAD4);

    for (int idx = tid; idx < IWQ * IWQ; idx += NT) {
        const int r = idx / IWQ, c = idx - r * IWQ;
        IN[r * QM::IWp + c] = src[r * DP4 + c];
    }
    __syncthreads();

    run_sigma_phases_q<5, true >(IN, FHs, A1s, tid);   // dP = 0
    __syncthreads();
    run_sigma_phases_q<4, false>(IN, FHs, A1s, tid);   // dP = 10 (scalar)
    __syncthreads();
    run_sigma_phases_q<3, false>(IN, FHs, A1s, tid);   // dP = 15 (scalar)

    finish_block(out, tid);
}

// ---------------- launcher ---------------------------------------------------

extern "C" void kernel_launch(void* const* d_in, const int* in_sizes, int n_in,
                              void* d_out, int out_size) {
    (void)in_sizes; (void)n_in; (void)out_size;
    const float* a = (const float*)d_in[0];
    const float* b = (const float*)d_in[1];
    float* out = (float*)d_out;

    // one-time host resources (created on the uncaptured correctness call)
    static cudaStream_t sB = nullptr;
    static cudaEvent_t eF = nullptr, eB = nullptr;
    if (!sB) {
        cudaStreamCreateWithFlags(&sB, cudaStreamNonBlocking);
        cudaEventCreateWithFlags(&eF, cudaEventDisableTiming);
        cudaEventCreateWithFlags(&eB, cudaEventDisableTiming);
        cudaFuncSetAttribute(fused_all_k,  cudaFuncAttributeMaxDynamicSharedMemorySize, MSz::BYTES);
        cudaFuncSetAttribute(fusedq_all_k, cudaFuncAttributeMaxDynamicSharedMemorySize, QM::BYTES);
    }

    // fork point for the side stream
    cudaEventRecord(eF, 0);
    cudaStreamWaitEvent(sB, eF, 0);

    // legacy stream: the dominant full-res kernel starts immediately
    fused_all_k<<<dim3(Ww / 64, Hh / 64, NCc), NT, MSz::BYTES>>>(a, b, out);

    // side stream: quarter pipeline runs concurrently (it is much shorter)
    down4_k<<<dim3(DP4, NCc), 256, 0, sB>>>(a, b);
    fusedq_all_k<<<dim3(W4 / 64, W4 / 64, NCc), NT, QM::BYTES, sB>>>(out);

    // join (capture requires it; the last finishing block wrote `out`)
    cudaEventRecord(eB, sB);
    cudaStreamWaitEvent(0, eB, 0);
}